// round 8
// baseline (speedup 1.0000x reference)
#include <cuda_runtime.h>
#include <math.h>

// SparseDimAttention, GB300 sm_103a — chunked 2-stream pipeline for L2 reuse.
// Stream A: scores_c  (continuous 276 MB DRAM stream, 4 chunks x 128 batches)
// Stream B: topk_c -> wsum_c  (wsum re-reads chunk's x from L2, overlapped with A)
// Then: head on stream A after join.

constexpr int Ll = 33, Dd = 4096, Pp = 64, Kk = 512, Hh = 128, Bb = 512;
constexpr int BINS = 1024;
constexpr int NCH = 4, CB = Bb / NCH;   // 4 chunks x 128 batches

__device__ float g_scores[(size_t)Bb * Dd];
__device__ float g_w[(size_t)Bb * Dd];
__device__ float g_y[(size_t)Bb * Ll];

__device__ __forceinline__ unsigned int fkey(float f) {
    unsigned int u = __float_as_uint(f);
    return u ^ ((u & 0x80000000u) ? 0xFFFFFFFFu : 0x80000000u); // ascending monotonic
}

// ---------------- scores: 4 CTAs per batch ----------------
__global__ void __launch_bounds__(256) scores_kernel(
    const float* __restrict__ x, const float* __restrict__ Wp,
    const float* __restrict__ bp, const float* __restrict__ ws,
    const float* __restrict__ bsc, int b0)
{
    __shared__ float v[Ll];
    __shared__ float s_c;
    const int tid = threadIdx.x;
    if (tid < Ll) {
        float a = 0.f;
        #pragma unroll
        for (int p = 0; p < Pp; ++p) a = fmaf(ws[p], Wp[p * Ll + tid], a);
        v[tid] = a;
    } else if (tid == Ll) {
        float a = bsc[0];
        #pragma unroll
        for (int p = 0; p < Pp; ++p) a = fmaf(ws[p], bp[p], a);
        s_c = a;
    }
    __syncthreads();

    const int b  = b0 + (blockIdx.x >> 2);
    const int d4 = ((blockIdx.x & 3) << 8) + tid;
    const float4* __restrict__ xb4 =
        reinterpret_cast<const float4*>(x) + (size_t)b * Ll * (Dd / 4) + d4;
    const float c = s_c;
    float4 acc = make_float4(c, c, c, c);
    #pragma unroll
    for (int l = 0; l < Ll; ++l) {
        float4 xv = xb4[(size_t)l * (Dd / 4)];
        const float vl = v[l];
        acc.x = fmaf(vl, xv.x, acc.x);
        acc.y = fmaf(vl, xv.y, acc.y);
        acc.z = fmaf(vl, xv.z, acc.z);
        acc.w = fmaf(vl, xv.w, acc.w);
    }
    reinterpret_cast<float4*>(g_scores)[(size_t)b * (Dd / 4) + d4] = acc;
}

// ---------------- topk: linear-bin select + softmax -> g_w ----------------
#define NT1 256
constexpr int CH1 = Dd / NT1;     // 16
constexpr int BPT = BINS / NT1;   // 4
constexpr int TREP = BINS / NT1;  // 4

__global__ void __launch_bounds__(NT1, 4) topk_kernel(int b0)
{
    __shared__ float sc[Dd];        // 16 KB
    __shared__ int   hist[BINS];    // 4 KB
    __shared__ float redmx[8], redmn[8], redf[8];
    __shared__ int   wsum_[8];
    __shared__ float s_m, s_lo, s_scale, s_invZ;
    __shared__ int   s_thr, s_rem, s_cnt, s_T;

    const int b = b0 + blockIdx.x, tid = threadIdx.x;
    const int lane = tid & 31, wid = tid >> 5;

    #pragma unroll
    for (int j = 0; j < BPT; ++j) hist[j * NT1 + tid] = 0;
    if (tid == 0) s_cnt = 0;

    // load scores (L2-hot) + min/max
    float mx = -INFINITY, mn = INFINITY;
    {
        const float4* gs4 = reinterpret_cast<const float4*>(g_scores) + (size_t)b * (Dd / 4);
        float4* sc4 = reinterpret_cast<float4*>(sc);
        #pragma unroll
        for (int g = 0; g < 4; ++g) {
            float4 v4 = gs4[g * NT1 + tid];
            sc4[g * NT1 + tid] = v4;
            mx = fmaxf(mx, fmaxf(fmaxf(v4.x, v4.y), fmaxf(v4.z, v4.w)));
            mn = fminf(mn, fminf(fminf(v4.x, v4.y), fminf(v4.z, v4.w)));
        }
    }
    #pragma unroll
    for (int o = 16; o > 0; o >>= 1) {
        mx = fmaxf(mx, __shfl_xor_sync(0xFFFFFFFFu, mx, o));
        mn = fminf(mn, __shfl_xor_sync(0xFFFFFFFFu, mn, o));
    }
    if (lane == 0) { redmx[wid] = mx; redmn[wid] = mn; }
    __syncthreads();
    if (tid < 8) {
        mx = redmx[tid]; mn = redmn[tid];
        #pragma unroll
        for (int o = 4; o > 0; o >>= 1) {
            mx = fmaxf(mx, __shfl_xor_sync(0x000000FFu, mx, o));
            mn = fminf(mn, __shfl_xor_sync(0x000000FFu, mn, o));
        }
        if (tid == 0) {
            s_m = mx; s_lo = mn;
            const float r = mx - mn;
            s_scale = (r > 0.f) ? ((float)(BINS - 1) / r) : 0.f;
        }
    }
    __syncthreads();

    const float lo = s_lo, scale = s_scale, mm = s_m;
    // value-uniform histogram
    #pragma unroll
    for (int it = 0; it < CH1; ++it) {
        const float s = sc[it * NT1 + tid];
        int bin = (int)((s - lo) * scale);
        bin = min(BINS - 1, max(0, bin));
        atomicAdd(&hist[bin], 1);
    }
    __syncthreads();

    // suffix scan: hist[i] = #elements with bin >= i
    {
        const int base = tid * BPT;
        int c[BPT];
        #pragma unroll
        for (int j = 0; j < BPT; ++j) c[j] = hist[base + j];
        #pragma unroll
        for (int j = BPT - 2; j >= 0; --j) c[j] += c[j + 1];
        int inc = c[0];
        #pragma unroll
        for (int o = 1; o < 32; o <<= 1) {
            int t = __shfl_up_sync(0xFFFFFFFFu, inc, o);
            if (lane >= o) inc += t;
        }
        if (lane == 31) wsum_[wid] = inc;
        __syncthreads();
        if (tid < 8) {
            int w = wsum_[tid];
            int iw = w;
            #pragma unroll
            for (int o = 1; o < 8; o <<= 1) {
                int t = __shfl_up_sync(0x000000FFu, iw, o);
                if (tid >= o) iw += t;
            }
            wsum_[tid] = iw - w;
            if (tid == 7) s_T = iw;
        }
        __syncthreads();
        const int S = s_T - (wsum_[wid] + inc);
        #pragma unroll
        for (int j = 0; j < BPT; ++j) hist[base + j] = S + c[j];
    }
    __syncthreads();

    // threshold bin
    #pragma unroll
    for (int j = 0; j < BPT; ++j) {
        const int i = tid * BPT + j;
        const int hv = hist[i];
        const int nx = (i < BINS - 1) ? hist[i + 1] : 0;
        if (hv >= Kk && nx < Kk) { s_thr = i; s_rem = Kk - nx; }
    }
    __syncthreads();
    const int thr = s_thr, rem = s_rem;

    // tie list (reuse hist)
    #pragma unroll
    for (int it = 0; it < CH1; ++it) {
        const int d = it * NT1 + tid;
        int bin = (int)((sc[d] - lo) * scale);
        bin = min(BINS - 1, max(0, bin));
        if (bin == thr) {
            int pos = atomicAdd(&s_cnt, 1);
            if (pos < BINS) hist[pos] = d;
        }
    }
    __syncthreads();
    const int cnt = s_cnt;
    const bool fast = (cnt <= BINS);

    // READ-ONLY: snapshot owner scores + rank ties by (key desc, idx asc)
    float sv[CH1];
    #pragma unroll
    for (int it = 0; it < CH1; ++it) sv[it] = sc[it * NT1 + tid];

    float twl[TREP]; int tdl[TREP];
    float twf[CH1];
    if (fast) {
        #pragma unroll
        for (int rep = 0; rep < TREP; ++rep) {
            const int i = rep * NT1 + tid;
            twl[rep] = 0.f; tdl[rep] = -1;
            if (i < cnt) {
                const int d = hist[i];
                const float s = sc[d];
                const unsigned int ke = fkey(s);
                int rank = 0;
                for (int j2 = 0; j2 < cnt; ++j2) {
                    const int d2 = hist[j2];
                    const unsigned int k2 = fkey(sc[d2]);
                    rank += (k2 > ke) || (k2 == ke && d2 < d);
                }
                tdl[rep] = d;
                twl[rep] = (rank < rem) ? expf(s - mm) : 0.f;
            }
        }
    } else { // exact fallback (degenerate data only)
        #pragma unroll
        for (int it = 0; it < CH1; ++it) {
            const int d = it * NT1 + tid;
            int bin = (int)((sv[it] - lo) * scale);
            bin = min(BINS - 1, max(0, bin));
            twf[it] = 0.f;
            if (bin == thr) {
                const unsigned int ke = fkey(sv[it]);
                int rank = 0;
                for (int d2 = 0; d2 < Dd; ++d2) {
                    const float s2 = sc[d2];
                    int b2i = (int)((s2 - lo) * scale);
                    b2i = min(BINS - 1, max(0, b2i));
                    if (b2i == thr) {
                        const unsigned int k2 = fkey(s2);
                        rank += (k2 > ke) || (k2 == ke && d2 < d);
                    }
                }
                twf[it] = (rank < rem) ? expf(sv[it] - mm) : 0.f;
            }
        }
    }
    __syncthreads();

    // WRITE: disjoint writers
    float zp = 0.f;
    #pragma unroll
    for (int it = 0; it < CH1; ++it) {
        const int d = it * NT1 + tid;
        int bin = (int)((sv[it] - lo) * scale);
        bin = min(BINS - 1, max(0, bin));
        if (bin != thr) {
            const float w = (bin > thr) ? expf(sv[it] - mm) : 0.f;
            sc[d] = w; zp += w;
        } else if (!fast) {
            sc[d] = twf[it]; zp += twf[it];
        }
    }
    if (fast) {
        #pragma unroll
        for (int rep = 0; rep < TREP; ++rep)
            if (tdl[rep] >= 0) { sc[tdl[rep]] = twl[rep]; zp += twl[rep]; }
    }
    #pragma unroll
    for (int o = 16; o > 0; o >>= 1) zp += __shfl_xor_sync(0xFFFFFFFFu, zp, o);
    if (lane == 0) redf[wid] = zp;
    __syncthreads();
    if (tid < 8) {
        zp = redf[tid];
        #pragma unroll
        for (int o = 4; o > 0; o >>= 1) zp += __shfl_xor_sync(0x000000FFu, zp, o);
        if (tid == 0) s_invZ = 1.f / zp;
    }
    __syncthreads();

    const float invZ = s_invZ;
    float4* gw4 = reinterpret_cast<float4*>(g_w) + (size_t)b * (Dd / 4);
    const float4* sc4r = reinterpret_cast<const float4*>(sc);
    #pragma unroll
    for (int g = 0; g < 4; ++g) {
        float4 wv = sc4r[g * NT1 + tid];
        wv.x *= invZ; wv.y *= invZ; wv.z *= invZ; wv.w *= invZ;
        gw4[g * NT1 + tid] = wv;
    }
}

// ---------------- wsum: one CTA per (l, b) ----------------
__global__ void __launch_bounds__(256) wsum_kernel(const float* __restrict__ x, int b0)
{
    __shared__ float red[8];
    const int l = blockIdx.x;
    const int b = b0 + blockIdx.y;
    const int tid = threadIdx.x;
    const int lane = tid & 31, wid = tid >> 5;

    const float4* __restrict__ xr4 =
        reinterpret_cast<const float4*>(x) + ((size_t)b * Ll + l) * (Dd / 4);
    const float4* __restrict__ wr4 =
        reinterpret_cast<const float4*>(g_w) + (size_t)b * (Dd / 4);

    float a0 = 0.f, a1 = 0.f, a2 = 0.f, a3 = 0.f;
    #pragma unroll
    for (int k = 0; k < 4; ++k) {
        const int i = k * 256 + tid;
        float4 wv = wr4[i];
        float4 xv = xr4[i];
        a0 = fmaf(wv.x, xv.x, a0);
        a1 = fmaf(wv.y, xv.y, a1);
        a2 = fmaf(wv.z, xv.z, a2);
        a3 = fmaf(wv.w, xv.w, a3);
    }
    float acc = (a0 + a1) + (a2 + a3);
    #pragma unroll
    for (int o = 16; o > 0; o >>= 1) acc += __shfl_xor_sync(0xFFFFFFFFu, acc, o);
    if (lane == 0) red[wid] = acc;
    __syncthreads();
    if (tid < 8) {
        acc = red[tid];
        #pragma unroll
        for (int o = 4; o > 0; o >>= 1) acc += __shfl_xor_sync(0x000000FFu, acc, o);
        if (tid == 0) g_y[(size_t)b * Ll + l] = acc;
    }
}

// ---------------- head: warp-per-batch ----------------
__global__ void __launch_bounds__(256) head_kernel(
    const float* __restrict__ Wp, const float* __restrict__ bp,
    const float* __restrict__ gamma, const float* __restrict__ beta,
    const float* __restrict__ W1, const float* __restrict__ b1,
    const float* __restrict__ W2, const float* __restrict__ b2,
    float* __restrict__ out)
{
    __shared__ float sWp[Pp * Ll];
    __shared__ float sW1[Hh * Pp];
    __shared__ float sW2[2 * Hh];
    __shared__ float sbp[Pp], sg[Pp], sbe[Pp], sb1[Hh], sb2[2];
    __shared__ float yw[8][Ll + 1];
    __shared__ float zw[8][Pp];
    const int tid = threadIdx.x;
    const int lane = tid & 31, wid = tid >> 5;

    for (int i = tid; i < Pp * Ll; i += 256) sWp[i] = Wp[i];
    for (int i = tid; i < Hh * Pp; i += 256) sW1[i] = W1[i];
    if (tid < 2 * Hh) sW2[tid] = W2[tid];
    if (tid < Pp) { sbp[tid] = bp[tid]; sg[tid] = gamma[tid]; sbe[tid] = beta[tid]; }
    if (tid < Hh) sb1[tid] = b1[tid];
    if (tid < 2) sb2[tid] = b2[tid];

    const int b = blockIdx.x * 8 + wid;
    for (int i = lane; i < Ll; i += 32) yw[wid][i] = g_y[(size_t)b * Ll + i];
    __syncthreads();

    float z0 = sbp[lane], z1 = sbp[lane + 32];
    #pragma unroll
    for (int l = 0; l < Ll; ++l) {
        const float y = yw[wid][l];
        z0 = fmaf(sWp[lane * Ll + l], y, z0);
        z1 = fmaf(sWp[(lane + 32) * Ll + l], y, z1);
    }
    float sum = z0 + z1;
    #pragma unroll
    for (int o = 16; o > 0; o >>= 1) sum += __shfl_xor_sync(0xFFFFFFFFu, sum, o);
    const float mu = sum * (1.f / 64.f);
    const float d0 = z0 - mu, d1 = z1 - mu;
    float sq = d0 * d0 + d1 * d1;
    #pragma unroll
    for (int o = 16; o > 0; o >>= 1) sq += __shfl_xor_sync(0xFFFFFFFFu, sq, o);
    const float rstd = rsqrtf(sq * (1.f / 64.f) + 1e-5f);
    zw[wid][lane]      = d0 * rstd * sg[lane] + sbe[lane];
    zw[wid][lane + 32] = d1 * rstd * sg[lane + 32] + sbe[lane + 32];
    __syncwarp();

    float a[4];
    #pragma unroll
    for (int k = 0; k < 4; ++k) {
        const int j = k * 32 + lane;
        float acc = sb1[j];
        #pragma unroll
        for (int p = 0; p < Pp; ++p) {
            const int pr = (p + lane) & (Pp - 1);
            acc = fmaf(sW1[j * Pp + pr], zw[wid][pr], acc);
        }
        a[k] = 0.5f * acc * (1.f + erff(acc * 0.70710678118654752f));
    }
    float o0 = 0.f, o1 = 0.f;
    #pragma unroll
    for (int k = 0; k < 4; ++k) {
        const int j = k * 32 + lane;
        o0 = fmaf(sW2[j], a[k], o0);
        o1 = fmaf(sW2[Hh + j], a[k], o1);
    }
    #pragma unroll
    for (int o = 16; o > 0; o >>= 1) {
        o0 += __shfl_xor_sync(0xFFFFFFFFu, o0, o);
        o1 += __shfl_xor_sync(0xFFFFFFFFu, o1, o);
    }
    if (lane == 0) {
        out[b * 2 + 0] = o0 + sb2[0];
        out[b * 2 + 1] = o1 + sb2[1];
    }
}

extern "C" void kernel_launch(void* const* d_in, const int* in_sizes, int n_in,
                              void* d_out, int out_size) {
    const float* x     = (const float*)d_in[0];
    const float* Wp    = (const float*)d_in[1];
    const float* bp    = (const float*)d_in[2];
    const float* ws    = (const float*)d_in[3];
    const float* bsc   = (const float*)d_in[4];
    const float* gamma = (const float*)d_in[5];
    const float* beta  = (const float*)d_in[6];
    const float* W1    = (const float*)d_in[7];
    const float* b1    = (const float*)d_in[8];
    const float* W2    = (const float*)d_in[9];
    const float* b2    = (const float*)d_in[10];
    float* out = (float*)d_out;

    // Lazily created once (host-side objects only; first call is the
    // non-captured correctness run). Reused identically on every call.
    static cudaStream_t sB = nullptr;
    static cudaEvent_t evS[NCH];
    static cudaEvent_t evJ = nullptr;
    if (sB == nullptr) {
        cudaStreamCreateWithFlags(&sB, cudaStreamNonBlocking);
        for (int c = 0; c < NCH; ++c)
            cudaEventCreateWithFlags(&evS[c], cudaEventDisableTiming);
        cudaEventCreateWithFlags(&evJ, cudaEventDisableTiming);
    }

    for (int c = 0; c < NCH; ++c) {
        const int b0 = c * CB;
        scores_kernel<<<CB * 4, 256, 0, 0>>>(x, Wp, bp, ws, bsc, b0);
        cudaEventRecord(evS[c], 0);
        cudaStreamWaitEvent(sB, evS[c], 0);
        topk_kernel<<<CB, NT1, 0, sB>>>(b0);
        wsum_kernel<<<dim3(Ll, CB), 256, 0, sB>>>(x, b0);
    }
    cudaEventRecord(evJ, sB);
    cudaStreamWaitEvent(0, evJ, 0);
    head_kernel<<<Bb / 8, 256, 0, 0>>>(Wp, bp, gamma, beta, W1, b1, W2, b2, out);
}

// round 9
// speedup vs baseline: 1.2726x; 1.2726x over previous
#include <cuda_runtime.h>
#include <math.h>

// SparseDimAttention, GB300 sm_103a — single-x-read mega kernel + tiny head.
// mega: 1 CTA per batch, 1 CTA/SM (smem pad). Phase1 streams x[b] (DRAM, 276 MB chip-wide)
//       computing scores in smem; select+softmax in smem; Phase5 re-reads x[b] from L2
//       (148 resident slices = 78 MB < 126 MB L2) -> y written directly. No g_w/g_scores.
// head: warp-per-batch MLP.

constexpr int Ll = 33, Dd = 4096, Pp = 64, Kk = 512, Hh = 128, Bb = 512;
constexpr int BINS = 1024;

__device__ float g_y[(size_t)Bb * Ll];

__device__ __forceinline__ unsigned int fkey(float f) {
    unsigned int u = __float_as_uint(f);
    return u ^ ((u & 0x80000000u) ? 0xFFFFFFFFu : 0x80000000u); // ascending monotonic
}

// ---------------- mega ----------------
#define NTM 512
constexpr int CHM = Dd / NTM;      // 8
constexpr int BPTM = BINS / NTM;   // 2
constexpr int TREPM = BINS / NTM;  // 2
constexpr int SMEM_BYTES = 128 * 1024;  // sc(16K)+hist(4K)+pad -> forces 1 CTA/SM

__global__ void __launch_bounds__(NTM, 1) mega_kernel(
    const float* __restrict__ x, const float* __restrict__ Wp,
    const float* __restrict__ bp, const float* __restrict__ ws,
    const float* __restrict__ bsc)
{
    extern __shared__ float dyn[];
    float* sc = dyn;                         // [Dd] scores -> weights
    int* hist = (int*)(dyn + Dd);            // [BINS]

    __shared__ float v[Ll];
    __shared__ float redmx[16], redmn[16], redf[16];
    __shared__ int   wsum_[16];
    __shared__ float s_c, s_m, s_lo, s_scale, s_invZ;
    __shared__ int   s_thr, s_rem, s_cnt, s_T;

    const int b = blockIdx.x, tid = threadIdx.x;
    const int lane = tid & 31, wid = tid >> 5;

    // fold projection: v[l] = sum_p ws[p]*Wp[p,l]; c = ws@bp + bs
    if (tid < Ll) {
        float a = 0.f;
        #pragma unroll
        for (int p = 0; p < Pp; ++p) a = fmaf(ws[p], Wp[p * Ll + tid], a);
        v[tid] = a;
    } else if (tid == Ll) {
        float a = bsc[0];
        #pragma unroll
        for (int p = 0; p < Pp; ++p) a = fmaf(ws[p], bp[p], a);
        s_c = a;
    }
    #pragma unroll
    for (int j = 0; j < BPTM; ++j) hist[j * NTM + tid] = 0;
    if (tid == 0) s_cnt = 0;
    __syncthreads();

    const float4* __restrict__ xb4 =
        reinterpret_cast<const float4*>(x) + (size_t)b * Ll * (Dd / 4);

    // ---- phase 1: stream x[b] from DRAM, scores into smem ----
    {
        const float cc = s_c;
        float4 a0 = make_float4(cc, cc, cc, cc);
        float4 a1 = make_float4(cc, cc, cc, cc);
        #pragma unroll 4
        for (int l = 0; l < Ll; ++l) {
            const float vl = v[l];
            const float4* row = xb4 + (size_t)l * (Dd / 4);
            float4 x0 = row[tid];
            float4 x1 = row[tid + NTM];
            a0.x = fmaf(vl, x0.x, a0.x); a0.y = fmaf(vl, x0.y, a0.y);
            a0.z = fmaf(vl, x0.z, a0.z); a0.w = fmaf(vl, x0.w, a0.w);
            a1.x = fmaf(vl, x1.x, a1.x); a1.y = fmaf(vl, x1.y, a1.y);
            a1.z = fmaf(vl, x1.z, a1.z); a1.w = fmaf(vl, x1.w, a1.w);
        }
        float4* sc4 = reinterpret_cast<float4*>(sc);
        sc4[tid] = a0;
        sc4[tid + NTM] = a1;
        float mx = fmaxf(fmaxf(a0.x, a0.y), fmaxf(a0.z, a0.w));
        mx = fmaxf(mx, fmaxf(fmaxf(a1.x, a1.y), fmaxf(a1.z, a1.w)));
        float mn = fminf(fminf(a0.x, a0.y), fminf(a0.z, a0.w));
        mn = fminf(mn, fminf(fminf(a1.x, a1.y), fminf(a1.z, a1.w)));
        #pragma unroll
        for (int o = 16; o > 0; o >>= 1) {
            mx = fmaxf(mx, __shfl_xor_sync(0xFFFFFFFFu, mx, o));
            mn = fminf(mn, __shfl_xor_sync(0xFFFFFFFFu, mn, o));
        }
        if (lane == 0) { redmx[wid] = mx; redmn[wid] = mn; }
    }
    __syncthreads();
    if (tid < 16) {
        float mx = redmx[tid], mn = redmn[tid];
        #pragma unroll
        for (int o = 8; o > 0; o >>= 1) {
            mx = fmaxf(mx, __shfl_xor_sync(0x0000FFFFu, mx, o));
            mn = fminf(mn, __shfl_xor_sync(0x0000FFFFu, mn, o));
        }
        if (tid == 0) {
            s_m = mx; s_lo = mn;
            const float r = mx - mn;
            s_scale = (r > 0.f) ? ((float)(BINS - 1) / r) : 0.f;
        }
    }
    __syncthreads();

    const float lo = s_lo, scale = s_scale, mm = s_m;
    // value-uniform histogram
    #pragma unroll
    for (int it = 0; it < CHM; ++it) {
        const float s = sc[it * NTM + tid];
        int bin = (int)((s - lo) * scale);
        bin = min(BINS - 1, max(0, bin));
        atomicAdd(&hist[bin], 1);
    }
    __syncthreads();

    // suffix scan: hist[i] = #elements with bin >= i
    {
        const int base = tid * BPTM;
        int c[BPTM];
        #pragma unroll
        for (int j = 0; j < BPTM; ++j) c[j] = hist[base + j];
        #pragma unroll
        for (int j = BPTM - 2; j >= 0; --j) c[j] += c[j + 1];
        int inc = c[0];
        #pragma unroll
        for (int o = 1; o < 32; o <<= 1) {
            int t = __shfl_up_sync(0xFFFFFFFFu, inc, o);
            if (lane >= o) inc += t;
        }
        if (lane == 31) wsum_[wid] = inc;
        __syncthreads();
        if (tid < 16) {
            int w = wsum_[tid];
            int iw = w;
            #pragma unroll
            for (int o = 1; o < 16; o <<= 1) {
                int t = __shfl_up_sync(0x0000FFFFu, iw, o);
                if (tid >= o) iw += t;
            }
            wsum_[tid] = iw - w;
            if (tid == 15) s_T = iw;
        }
        __syncthreads();
        const int S = s_T - (wsum_[wid] + inc);
        #pragma unroll
        for (int j = 0; j < BPTM; ++j) hist[base + j] = S + c[j];
    }
    __syncthreads();

    // threshold bin
    #pragma unroll
    for (int j = 0; j < BPTM; ++j) {
        const int i = tid * BPTM + j;
        const int hv = hist[i];
        const int nx = (i < BINS - 1) ? hist[i + 1] : 0;
        if (hv >= Kk && nx < Kk) { s_thr = i; s_rem = Kk - nx; }
    }
    __syncthreads();
    const int thr = s_thr, rem = s_rem;

    // tie list (reuse hist)
    #pragma unroll
    for (int it = 0; it < CHM; ++it) {
        const int d = it * NTM + tid;
        int bin = (int)((sc[d] - lo) * scale);
        bin = min(BINS - 1, max(0, bin));
        if (bin == thr) {
            int pos = atomicAdd(&s_cnt, 1);
            if (pos < BINS) hist[pos] = d;
        }
    }
    __syncthreads();
    const int cnt = s_cnt;
    const bool fast = (cnt <= BINS);

    // READ-ONLY: snapshot owner scores + rank ties by (key desc, idx asc)
    float sv[CHM];
    #pragma unroll
    for (int it = 0; it < CHM; ++it) sv[it] = sc[it * NTM + tid];

    float twl[TREPM]; int tdl[TREPM];
    float twf[CHM];
    if (fast) {
        #pragma unroll
        for (int rep = 0; rep < TREPM; ++rep) {
            const int i = rep * NTM + tid;
            twl[rep] = 0.f; tdl[rep] = -1;
            if (i < cnt) {
                const int d = hist[i];
                const float s = sc[d];
                const unsigned int ke = fkey(s);
                int rank = 0;
                for (int j2 = 0; j2 < cnt; ++j2) {
                    const int d2 = hist[j2];
                    const unsigned int k2 = fkey(sc[d2]);
                    rank += (k2 > ke) || (k2 == ke && d2 < d);
                }
                tdl[rep] = d;
                twl[rep] = (rank < rem) ? expf(s - mm) : 0.f;
            }
        }
    } else { // exact fallback (degenerate data only)
        #pragma unroll
        for (int it = 0; it < CHM; ++it) {
            const int d = it * NTM + tid;
            int bin = (int)((sv[it] - lo) * scale);
            bin = min(BINS - 1, max(0, bin));
            twf[it] = 0.f;
            if (bin == thr) {
                const unsigned int ke = fkey(sv[it]);
                int rank = 0;
                for (int d2 = 0; d2 < Dd; ++d2) {
                    const float s2 = sc[d2];
                    int b2i = (int)((s2 - lo) * scale);
                    b2i = min(BINS - 1, max(0, b2i));
                    if (b2i == thr) {
                        const unsigned int k2 = fkey(s2);
                        rank += (k2 > ke) || (k2 == ke && d2 < d);
                    }
                }
                twf[it] = (rank < rem) ? expf(sv[it] - mm) : 0.f;
            }
        }
    }
    __syncthreads();   // all sc reads done before writes

    // WRITE: disjoint writers, unnormalized weights into sc
    float zp = 0.f;
    #pragma unroll
    for (int it = 0; it < CHM; ++it) {
        const int d = it * NTM + tid;
        int bin = (int)((sv[it] - lo) * scale);
        bin = min(BINS - 1, max(0, bin));
        if (bin != thr) {
            const float w = (bin > thr) ? expf(sv[it] - mm) : 0.f;
            sc[d] = w; zp += w;
        } else if (!fast) {
            sc[d] = twf[it]; zp += twf[it];
        }
    }
    if (fast) {
        #pragma unroll
        for (int rep = 0; rep < TREPM; ++rep)
            if (tdl[rep] >= 0) { sc[tdl[rep]] = twl[rep]; zp += twl[rep]; }
    }
    #pragma unroll
    for (int o = 16; o > 0; o >>= 1) zp += __shfl_xor_sync(0xFFFFFFFFu, zp, o);
    if (lane == 0) redf[wid] = zp;
    __syncthreads();
    if (tid < 16) {
        zp = redf[tid];
        #pragma unroll
        for (int o = 8; o > 0; o >>= 1) zp += __shfl_xor_sync(0x0000FFFFu, zp, o);
        if (tid == 0) s_invZ = 1.f / zp;
    }
    __syncthreads();

    // ---- phase 5: y[l] = invZ * sum_d w[d]*x[b,l,d]  (x[b] re-read from L2) ----
    {
        const float invZ = s_invZ;
        const float4* sc4 = reinterpret_cast<const float4*>(sc);
        for (int l = wid; l < Ll; l += 16) {
            const float4* __restrict__ row = xb4 + (size_t)l * (Dd / 4);
            float a0 = 0.f, a1 = 0.f, a2 = 0.f, a3 = 0.f;
            #pragma unroll 4
            for (int i = lane; i < Dd / 4; i += 32) {
                float4 wv = sc4[i];
                float4 xv = row[i];
                a0 = fmaf(wv.x, xv.x, a0);
                a1 = fmaf(wv.y, xv.y, a1);
                a2 = fmaf(wv.z, xv.z, a2);
                a3 = fmaf(wv.w, xv.w, a3);
            }
            float acc = (a0 + a1) + (a2 + a3);
            #pragma unroll
            for (int o = 16; o > 0; o >>= 1) acc += __shfl_xor_sync(0xFFFFFFFFu, acc, o);
            if (lane == 0) g_y[(size_t)b * Ll + l] = acc * invZ;
        }
    }
}

// ---------------- head: warp-per-batch (8 batches/CTA) ----------------
__global__ void __launch_bounds__(256) head_kernel(
    const float* __restrict__ Wp, const float* __restrict__ bp,
    const float* __restrict__ gamma, const float* __restrict__ beta,
    const float* __restrict__ W1, const float* __restrict__ b1,
    const float* __restrict__ W2, const float* __restrict__ b2,
    float* __restrict__ out)
{
    __shared__ float sWp[Pp * Ll];
    __shared__ float sW1[Hh * Pp];
    __shared__ float sW2[2 * Hh];
    __shared__ float sbp[Pp], sg[Pp], sbe[Pp], sb1[Hh], sb2[2];
    __shared__ float yw[8][Ll + 1];
    __shared__ float zw[8][Pp];
    const int tid = threadIdx.x;
    const int lane = tid & 31, wid = tid >> 5;

    for (int i = tid; i < Pp * Ll; i += 256) sWp[i] = Wp[i];
    for (int i = tid; i < Hh * Pp; i += 256) sW1[i] = W1[i];
    if (tid < 2 * Hh) sW2[tid] = W2[tid];
    if (tid < Pp) { sbp[tid] = bp[tid]; sg[tid] = gamma[tid]; sbe[tid] = beta[tid]; }
    if (tid < Hh) sb1[tid] = b1[tid];
    if (tid < 2) sb2[tid] = b2[tid];

    const int b = blockIdx.x * 8 + wid;
    for (int i = lane; i < Ll; i += 32) yw[wid][i] = g_y[(size_t)b * Ll + i];
    __syncthreads();

    float z0 = sbp[lane], z1 = sbp[lane + 32];
    #pragma unroll
    for (int l = 0; l < Ll; ++l) {
        const float y = yw[wid][l];
        z0 = fmaf(sWp[lane * Ll + l], y, z0);
        z1 = fmaf(sWp[(lane + 32) * Ll + l], y, z1);
    }
    float sum = z0 + z1;
    #pragma unroll
    for (int o = 16; o > 0; o >>= 1) sum += __shfl_xor_sync(0xFFFFFFFFu, sum, o);
    const float mu = sum * (1.f / 64.f);
    const float d0 = z0 - mu, d1 = z1 - mu;
    float sq = d0 * d0 + d1 * d1;
    #pragma unroll
    for (int o = 16; o > 0; o >>= 1) sq += __shfl_xor_sync(0xFFFFFFFFu, sq, o);
    const float rstd = rsqrtf(sq * (1.f / 64.f) + 1e-5f);
    zw[wid][lane]      = d0 * rstd * sg[lane] + sbe[lane];
    zw[wid][lane + 32] = d1 * rstd * sg[lane + 32] + sbe[lane + 32];
    __syncwarp();

    float a[4];
    #pragma unroll
    for (int k = 0; k < 4; ++k) {
        const int j = k * 32 + lane;
        float acc = sb1[j];
        #pragma unroll
        for (int p = 0; p < Pp; ++p) {
            const int pr = (p + lane) & (Pp - 1);
            acc = fmaf(sW1[j * Pp + pr], zw[wid][pr], acc);
        }
        a[k] = 0.5f * acc * (1.f + erff(acc * 0.70710678118654752f));
    }
    float o0 = 0.f, o1 = 0.f;
    #pragma unroll
    for (int k = 0; k < 4; ++k) {
        const int j = k * 32 + lane;
        o0 = fmaf(sW2[j], a[k], o0);
        o1 = fmaf(sW2[Hh + j], a[k], o1);
    }
    #pragma unroll
    for (int o = 16; o > 0; o >>= 1) {
        o0 += __shfl_xor_sync(0xFFFFFFFFu, o0, o);
        o1 += __shfl_xor_sync(0xFFFFFFFFu, o1, o);
    }
    if (lane == 0) {
        out[b * 2 + 0] = o0 + sb2[0];
        out[b * 2 + 1] = o1 + sb2[1];
    }
}

extern "C" void kernel_launch(void* const* d_in, const int* in_sizes, int n_in,
                              void* d_out, int out_size) {
    const float* x     = (const float*)d_in[0];
    const float* Wp    = (const float*)d_in[1];
    const float* bp    = (const float*)d_in[2];
    const float* ws    = (const float*)d_in[3];
    const float* bsc   = (const float*)d_in[4];
    const float* gamma = (const float*)d_in[5];
    const float* beta  = (const float*)d_in[6];
    const float* W1    = (const float*)d_in[7];
    const float* b1    = (const float*)d_in[8];
    const float* W2    = (const float*)d_in[9];
    const float* b2    = (const float*)d_in[10];
    float* out = (float*)d_out;

    cudaFuncSetAttribute(mega_kernel, cudaFuncAttributeMaxDynamicSharedMemorySize, SMEM_BYTES);
    mega_kernel<<<Bb, NTM, SMEM_BYTES>>>(x, Wp, bp, ws, bsc);
    head_kernel<<<Bb / 8, 256>>>(Wp, bp, gamma, beta, W1, b1, W2, b2, out);
}